// round 9
// baseline (speedup 1.0000x reference)
#include <cuda_runtime.h>

// ---------------------------------------------------------------------------
// TiDHy reference collapses analytically (validated R3-R6, rel_err ~1e-7):
//   r zeroed each step, r2 stays zero  =>  hypernet/temporal path dead.
//   sl_rhat = (1/B) * sum_{b,t=0..T-1,d} (b_sd[d]-X[b,t,d])^2
//   sl_rbar = (1/B) * sum_{b,t=1..T-1,d} (b_sd[d]-X[b,t,d])^2
//   temp_loss = r2_losses = 0; r0, r2 outputs = zeros.
//
// R7: ONE graph node (each extra node costs ~2us fixed: R6's memset ate its
// own savings). The R6 kernel body (fast: 7.26us) is kept; the memset is
// replaced by in-kernel zero-fill of out[2..), and the scalar combine goes
// RED.F32 -> __device__ scratch + self-wrapping ticket; the last block
// copies scratch->out[0..1] and resets scratch for the next graph replay.
// ---------------------------------------------------------------------------

static constexpr int Bn   = 128;
static constexpr int T    = 32;
static constexpr int D    = 512;
static constexpr int N4   = Bn * T * D / 4;     // 524288 float4 (8 MB)
static constexpr int BLK  = 256;
static constexpr int GRID = 1024;               // 262144 threads, single wave
static constexpr int HALF = GRID * BLK;         // 262144 = N4/2

__device__ float        g_acc[2];               // [0]=sl_rhat, [1]=sl_rbar (pre-scaled)
__device__ unsigned int g_done;                 // self-wrapping completion ticket

__global__ __launch_bounds__(BLK)
void tidhy_fused_onenode(const float4* __restrict__ X4,
                         const float4* __restrict__ bsd4,
                         float* __restrict__ out, int out_size)
{
    const int tid = blockIdx.x * BLK + threadIdx.x;

    // ---- zero-fill out[2..out_size): temp_loss, r2_losses, r0, r2 ----
    for (int i = 2 + tid; i < out_size; i += HALF)
        out[i] = 0.0f;

    // ---- two front-batched coalesced loads per thread ----
    // HALF/128 = 2048 ≡ 0 (mod 32): both indices share t and d4.
    float4 x0 = X4[tid];
    float4 x1 = X4[tid + HALF];
    float4 b  = bsd4[tid & (D / 4 - 1)];        // 2 KB, L1/L2 broadcast
    const int t = (tid >> 7) & (T - 1);

    float a0 = b.x - x0.x, a1 = b.y - x0.y, a2 = b.z - x0.z, a3 = b.w - x0.w;
    float c0 = b.x - x1.x, c1 = b.y - x1.y, c2 = b.z - x1.z, c3 = b.w - x1.w;
    float v = a0*a0 + a1*a1 + a2*a2 + a3*a3
            + c0*c0 + c1*c1 + c2*c2 + c3*c3;
    float v0 = (t == 0) ? v : 0.0f;

    // ---- warp tree reduce (two sums pipelined) ----
    #pragma unroll
    for (int o = 16; o > 0; o >>= 1) {
        v  += __shfl_down_sync(0xffffffffu, v,  o);
        v0 += __shfl_down_sync(0xffffffffu, v0, o);
    }

    __shared__ float sh_all[8], sh_t0[8];
    const int lane = threadIdx.x & 31;
    const int wrp  = threadIdx.x >> 5;
    if (lane == 0) { sh_all[wrp] = v; sh_t0[wrp] = v0; }
    __syncthreads();

    if (wrp != 0) return;

    v  = (lane < BLK / 32) ? sh_all[lane] : 0.0f;
    v0 = (lane < BLK / 32) ? sh_t0[lane]  : 0.0f;
    #pragma unroll
    for (int o = 4; o > 0; o >>= 1) {
        v  += __shfl_down_sync(0x000000ffu, v,  o);
        v0 += __shfl_down_sync(0x000000ffu, v0, o);
    }

    // ---- publish partials (fire-and-forget RED.F32) + ticket ----
    unsigned int ticket = 0;
    if (lane == 0) {
        constexpr float invB = 1.0f / (float)Bn;
        atomicAdd(&g_acc[0], v * invB);           // sl_rhat partial
        atomicAdd(&g_acc[1], (v - v0) * invB);    // sl_rbar partial
        __threadfence();                          // REDs visible before ticket
        // wraps to 0 when old == GRID-1 → self-resets for next replay
        ticket = atomicInc(&g_done, GRID - 1);
    }
    ticket = __shfl_sync(0xffffffffu, ticket, 0);
    if (ticket != GRID - 1) return;

    // ---- last block: copy scratch -> out, reset scratch for next replay ----
    if (lane == 0) {
        __threadfence();                          // acquire: all REDs visible
        out[0] = g_acc[0];                        // sl_rhat  (t = 0..T-1)
        out[1] = g_acc[1];                        // sl_rbar  (t = 1..T-1)
        g_acc[0] = 0.0f;
        g_acc[1] = 0.0f;
    }
}

extern "C" void kernel_launch(void* const* d_in, const int* in_sizes, int n_in,
                              void* d_out, int out_size)
{
    // metadata order: X, rng, W_sd, b_sd, W_h1, b_h1, ln_scale, ln_bias,
    //                 W_h2, b_h2, W_h3, b_h3, temporal
    const float4* X4   = (const float4*)d_in[0];
    const float4* bsd4 = (const float4*)d_in[3];
    float* out = (float*)d_out;

    tidhy_fused_onenode<<<GRID, BLK>>>(X4, bsd4, out, out_size);
}

// round 10
// speedup vs baseline: 1.2638x; 1.2638x over previous
#include <cuda_runtime.h>

// ---------------------------------------------------------------------------
// TiDHy reference collapses analytically (validated R3-R7, rel_err ~1e-7):
//   r zeroed each step, r2 stays zero  =>  hypernet/temporal path dead.
//   sl_rhat = (1/B) * sum_{b,t=0..T-1,d} (b_sd[d]-X[b,t,d])^2
//   sl_rbar = (1/B) * sum_{b,t=1..T-1,d} (b_sd[d]-X[b,t,d])^2
//   temp_loss = r2_losses = 0; r0, r2 outputs = zeros.
//
// R8: one graph node; combine-tail shrunk. R7 showed the same-address ticket
// atomicInc serializes ~linearly in participant count (1024 tickets ~= +2.5us
// kernel). Now: 128 blocks x 1024 threads, 4 front-batched float4 loads per
// thread (MLP=4), 128-participant ticket, last block publishes scalars and
// resets scratch for the next graph replay.
// ---------------------------------------------------------------------------

static constexpr int Bn   = 128;
static constexpr int T    = 32;
static constexpr int D    = 512;
static constexpr int N4   = Bn * T * D / 4;     // 524288 float4 (8 MB)
static constexpr int BLK  = 1024;
static constexpr int GRID = 128;                // 131072 threads
static constexpr int NT   = GRID * BLK;         // 131072 = N4/4
// stride NT float4: NT/128 = 1024 ≡ 0 (mod 32) → all 4 loads per thread
// share the same t = (i>>7)&31 and the same d4 = i&127.

__device__ float        g_acc[2];               // [0]=sl_rhat, [1]=sl_rbar (pre-scaled)
__device__ unsigned int g_done;                 // self-wrapping completion ticket

__global__ __launch_bounds__(BLK)
void tidhy_r8_kernel(const float4* __restrict__ X4,
                     const float4* __restrict__ bsd4,
                     float* __restrict__ out, int out_size)
{
    const int tid = blockIdx.x * BLK + threadIdx.x;

    // ---- 4 front-batched coalesced loads (MLP=4) ----
    float4 x0 = X4[tid];
    float4 x1 = X4[tid + NT];
    float4 x2 = X4[tid + 2 * NT];
    float4 x3 = X4[tid + 3 * NT];
    float4 b  = bsd4[tid & (D / 4 - 1)];        // 2 KB, L1/L2 broadcast

    // ---- zero-fill out[2..out_size) while loads are in flight ----
    for (int i = 2 + tid; i < out_size; i += NT)
        out[i] = 0.0f;

    const int t = (tid >> 7) & (T - 1);

    float a0 = b.x - x0.x, a1 = b.y - x0.y, a2 = b.z - x0.z, a3 = b.w - x0.w;
    float c0 = b.x - x1.x, c1 = b.y - x1.y, c2 = b.z - x1.z, c3 = b.w - x1.w;
    float d0 = b.x - x2.x, d1 = b.y - x2.y, d2 = b.z - x2.z, d3 = b.w - x2.w;
    float e0 = b.x - x3.x, e1 = b.y - x3.y, e2 = b.z - x3.z, e3 = b.w - x3.w;

    float v = (a0*a0 + a1*a1 + a2*a2 + a3*a3)
            + (c0*c0 + c1*c1 + c2*c2 + c3*c3)
            + (d0*d0 + d1*d1 + d2*d2 + d3*d3)
            + (e0*e0 + e1*e1 + e2*e2 + e3*e3);
    float v0 = (t == 0) ? v : 0.0f;

    // ---- warp tree reduce (two sums pipelined) ----
    #pragma unroll
    for (int o = 16; o > 0; o >>= 1) {
        v  += __shfl_down_sync(0xffffffffu, v,  o);
        v0 += __shfl_down_sync(0xffffffffu, v0, o);
    }

    __shared__ float sh_all[32], sh_t0[32];
    const int lane = threadIdx.x & 31;
    const int wrp  = threadIdx.x >> 5;
    if (lane == 0) { sh_all[wrp] = v; sh_t0[wrp] = v0; }
    __syncthreads();

    if (wrp != 0) return;

    v  = sh_all[lane];
    v0 = sh_t0[lane];
    #pragma unroll
    for (int o = 16; o > 0; o >>= 1) {
        v  += __shfl_down_sync(0xffffffffu, v,  o);
        v0 += __shfl_down_sync(0xffffffffu, v0, o);
    }

    // ---- publish partials (fire-and-forget RED.F32) + 128-wide ticket ----
    unsigned int ticket = 0;
    if (lane == 0) {
        constexpr float invB = 1.0f / (float)Bn;
        atomicAdd(&g_acc[0], v * invB);           // sl_rhat partial
        atomicAdd(&g_acc[1], (v - v0) * invB);    // sl_rbar partial
        __threadfence();                          // REDs visible before ticket
        ticket = atomicInc(&g_done, GRID - 1);    // wraps → self-reset per replay
    }
    ticket = __shfl_sync(0xffffffffu, ticket, 0);
    if (ticket != GRID - 1) return;

    // ---- last block: publish scalars, reset scratch for next replay ----
    if (lane == 0) {
        __threadfence();                          // acquire: all REDs visible
        out[0] = g_acc[0];                        // sl_rhat  (t = 0..T-1)
        out[1] = g_acc[1];                        // sl_rbar  (t = 1..T-1)
        g_acc[0] = 0.0f;
        g_acc[1] = 0.0f;
    }
}

extern "C" void kernel_launch(void* const* d_in, const int* in_sizes, int n_in,
                              void* d_out, int out_size)
{
    // metadata order: X, rng, W_sd, b_sd, W_h1, b_h1, ln_scale, ln_bias,
    //                 W_h2, b_h2, W_h3, b_h3, temporal
    const float4* X4   = (const float4*)d_in[0];
    const float4* bsd4 = (const float4*)d_in[3];
    float* out = (float*)d_out;

    tidhy_r8_kernel<<<GRID, BLK>>>(X4, bsd4, out, out_size);
}